// round 13
// baseline (speedup 1.0000x reference)
#include <cuda_runtime.h>
#include <cuda_bf16.h>
#include <cuda_fp16.h>
#include <math.h>
#include <stdint.h>

#define BB 64
#define LL 900
#define DD 64
#define MT 128
#define NT 64
#define NKT 15
#define SC 0.180336893f   // 0.125 * log2(e)

#define STR  72           // 16-bit elems per smem row (144B)
#define STRB 144

// smem byte offsets
#define SQ    0           // Q fp16 single: 128 x 144B
#define SK    18432       // K fp16 single: 64 x 144B
#define SVHI  27648
#define SVLO  36864
#define SP    46080       // P fp16 single: 128 x 144B
#define SSL   64512
#define SSINV 65024
#define SMEM_BYTES 65536

#define NELEM (BB * LL * DD)

__device__ __half g_qh[NELEM];
__device__ __half g_kh[NELEM];
__device__ __half g_vhi[NELEM], g_vlo[NELEM];

static __device__ __forceinline__ uint32_t smem_u32(const void* p) {
    uint32_t a;
    asm("{ .reg .u64 t; cvta.to.shared.u64 t, %1; cvt.u32.u64 %0, t; }" : "=r"(a) : "l"(p));
    return a;
}
static __device__ __forceinline__ float ex2f(float x) {
    float r; asm("ex2.approx.ftz.f32 %0, %1;" : "=f"(r) : "f"(x)); return r;
}
static __device__ __forceinline__ uint32_t cvt2h(float hi, float lo) {
    uint32_t r; asm("cvt.rn.f16x2.f32 %0, %1, %2;" : "=r"(r) : "f"(hi), "f"(lo)); return r;
}
static __device__ __forceinline__ void cpa16(uint32_t dst, const void* src, int sz) {
    asm volatile("cp.async.cg.shared.global [%0], [%1], 16, %2;"
                 :: "r"(dst), "l"(src), "r"(sz) : "memory");
}
#define CP_COMMIT() asm volatile("cp.async.commit_group;" ::: "memory")
#define CP_WAIT0()  asm volatile("cp.async.wait_group 0;" ::: "memory")

#define LDM4(r, a) \
    asm volatile("ldmatrix.sync.aligned.m8n8.x4.shared.b16 {%0,%1,%2,%3}, [%4];" \
        : "=r"((r)[0]), "=r"((r)[1]), "=r"((r)[2]), "=r"((r)[3]) : "r"(a))
#define LDM4T(r, a) \
    asm volatile("ldmatrix.sync.aligned.m8n8.x4.trans.shared.b16 {%0,%1,%2,%3}, [%4];" \
        : "=r"((r)[0]), "=r"((r)[1]), "=r"((r)[2]), "=r"((r)[3]) : "r"(a))
#define MMAH(d, a, b0, b1) \
    asm volatile("mma.sync.aligned.m16n8k16.row.col.f32.f16.f16.f32 " \
        "{%0,%1,%2,%3}, {%4,%5,%6,%7}, {%8,%9}, {%0,%1,%2,%3};" \
        : "+f"((d)[0]), "+f"((d)[1]), "+f"((d)[2]), "+f"((d)[3]) \
        : "r"((a)[0]), "r"((a)[1]), "r"((a)[2]), "r"((a)[3]), "r"(b0), "r"(b1))

// ---------- precvt: q,k -> fp16 single;  v -> fp16 hi/lo ----------
__global__ __launch_bounds__(256)
void precvt(const float* __restrict__ q, const float* __restrict__ k,
            const float* __restrict__ v)
{
    const int N4 = NELEM / 4;
    int i = blockIdx.x * blockDim.x + threadIdx.x;
    if (i >= 3 * N4) return;
    int t  = i / N4;
    int i4 = i - t * N4;
    if (t < 2) {
        float4 val = ((const float4*)(t == 0 ? q : k))[i4];
        uint32_t a01 = cvt2h(val.y, val.x);
        uint32_t a23 = cvt2h(val.w, val.z);
        ((uint2*)(t == 0 ? g_qh : g_kh))[i4] = make_uint2(a01, a23);
    } else {
        float4 val = ((const float4*)v)[i4];
        __half h0 = __float2half(val.x), h1 = __float2half(val.y);
        __half h2 = __float2half(val.z), h3 = __float2half(val.w);
        __half l0 = __float2half(val.x - __half2float(h0));
        __half l1 = __float2half(val.y - __half2float(h1));
        __half l2 = __float2half(val.z - __half2float(h2));
        __half l3 = __float2half(val.w - __half2float(h3));
        __half2 hv0 = __halves2half2(h0, h1), hv1 = __halves2half2(h2, h3);
        __half2 lv0 = __halves2half2(l0, l1), lv1 = __halves2half2(l2, l3);
        ((uint2*)g_vhi)[i4] = make_uint2(*(uint32_t*)&hv0, *(uint32_t*)&hv1);
        ((uint2*)g_vlo)[i4] = make_uint2(*(uint32_t*)&lv0, *(uint32_t*)&lv1);
    }
}

// ---------- fused attention (incl. warp-banded coalesced score rescale) ----------
__global__ void __launch_bounds__(256, 2)
attn_mma(const int* __restrict__ dur, float* __restrict__ out, float* __restrict__ score)
{
    extern __shared__ char s[];
    const uint32_t sb = smem_u32(s);

    const int tid = threadIdx.x;
    const int l   = tid & 31;
    const int wid = tid >> 5;
    const int mi  = wid >> 1;
    const int ni  = wid & 1;
    const int b   = blockIdx.y;
    const int q0  = blockIdx.x * MT;
    const int durb = dur[b];
    const size_t bi = (size_t)b * LL * DD;

    float* Sb = score + (size_t)b * LL * LL;

    if (tid < 128) *(float*)(s + SSL + tid * 4) = 0.f;

    // ---- prologue: cp.async Q + K0 + V0(hi/lo) ----
    #pragma unroll
    for (int w = 0; w < 4; w++) {
        int c = tid + 256 * w;
        int r = c >> 3, ch = c & 7;
        int rg = q0 + r;
        int rc = rg < LL ? rg : LL - 1;
        cpa16(sb + SQ + r * STRB + ch * 16,
              g_qh + bi + (size_t)rc * DD + ch * 8, rg < LL ? 16 : 0);
    }
    #pragma unroll
    for (int w = 0; w < 2; w++) {
        int c = tid + 256 * w;
        int r = c >> 3, ch = c & 7;
        cpa16(sb + SK + r * STRB + ch * 16, g_kh + bi + (size_t)r * DD + ch * 8, 16);
    }
    #pragma unroll
    for (int w = 0; w < 4; w++) {
        int c = tid + 256 * w;
        int buf = c >> 9;
        int r = (c >> 3) & 63, ch = c & 7;
        const __half* base = buf ? g_vlo : g_vhi;
        cpa16(sb + (buf ? SVLO : SVHI) + r * STRB + ch * 16,
              base + bi + (size_t)r * DD + ch * 8, 16);
    }
    CP_COMMIT();

    float oacc[2][4][4];
    #pragma unroll
    for (int a = 0; a < 2; a++)
        #pragma unroll
        for (int nb = 0; nb < 4; nb++)
            #pragma unroll
            for (int j = 0; j < 4; j++) oacc[a][nb][j] = 0.f;
    float rs[2][2] = {{0.f, 0.f}, {0.f, 0.f}};

    const uint32_t aSel = (l & 16) ? 16u : 0u;
    const uint32_t bRow = (l & 7) + ((l & 16) ? 8 : 0);
    const uint32_t bSel = (l & 8) ? 16u : 0u;
    const uint32_t aRow = (l & 15);

    for (int kt = 0; kt < NKT; kt++) {
        const int c0t = kt * NT;
        CP_WAIT0();
        __syncthreads();

        // ---- GEMM1: S = Q K^T (single fp16) ----
        float sacc[2][4][4];
        #pragma unroll
        for (int a = 0; a < 2; a++)
            #pragma unroll
            for (int nb = 0; nb < 4; nb++)
                #pragma unroll
                for (int j = 0; j < 4; j++) sacc[a][nb][j] = 0.f;

        #pragma unroll
        for (int ks = 0; ks < 4; ks++) {
            const uint32_t kb = ks * 32;
            uint32_t qa[2][4], kf[2][4];
            #pragma unroll
            for (int a = 0; a < 2; a++) {
                uint32_t ro = (mi * 32 + a * 16 + aRow) * STRB + kb + aSel;
                LDM4(qa[a], sb + SQ + ro);
            }
            #pragma unroll
            for (int np = 0; np < 2; np++) {
                uint32_t ro = (ni * 32 + np * 16 + bRow) * STRB + kb + bSel;
                LDM4(kf[np], sb + SK + ro);
            }
            #pragma unroll
            for (int a = 0; a < 2; a++)
                #pragma unroll
                for (int np = 0; np < 2; np++) {
                    MMAH(sacc[a][2*np],   qa[a], kf[np][0], kf[np][1]);
                    MMAH(sacc[a][2*np+1], qa[a], kf[np][2], kf[np][3]);
                }
        }

        // ---- epilogue: p = exp(mask(S*scale)); P(fp16)->smem, p->score (unnormalized) ----
        #pragma unroll
        for (int a = 0; a < 2; a++) {
            const int R0  = mi * 32 + a * 16 + (l >> 2);
            const int r0g = q0 + R0, r1g = r0g + 8;
            #pragma unroll
            for (int nb = 0; nb < 4; nb++) {
                const int col = ni * 32 + nb * 8 + 2 * (l & 3);
                const int cg  = c0t + col;
                float t0 = sacc[a][nb][0] * SC, t1 = sacc[a][nb][1] * SC;
                float t2 = sacc[a][nb][2] * SC, t3 = sacc[a][nb][3] * SC;
                if (r0g >= durb || cg     >= durb) t0 = 0.f;
                if (r0g >= durb || cg + 1 >= durb) t1 = 0.f;
                if (r1g >= durb || cg     >= durb) t2 = 0.f;
                if (r1g >= durb || cg + 1 >= durb) t3 = 0.f;
                float p0 = ex2f(t0), p1 = ex2f(t1), p2 = ex2f(t2), p3 = ex2f(t3);
                if (cg >= LL) { p0 = 0.f; p1 = 0.f; p2 = 0.f; p3 = 0.f; }
                rs[a][0] += p0 + p1;
                rs[a][1] += p2 + p3;
                uint32_t o0 = (R0 * STR + col) * 2;
                uint32_t o1 = ((R0 + 8) * STR + col) * 2;
                *(uint32_t*)(s + SP + o0) = cvt2h(p1, p0);
                *(uint32_t*)(s + SP + o1) = cvt2h(p3, p2);
                if (cg < LL) {
                    if (r0g < LL) *(float2*)(Sb + (size_t)r0g * LL + cg) = make_float2(p0, p1);
                    if (r1g < LL) *(float2*)(Sb + (size_t)r1g * LL + cg) = make_float2(p2, p3);
                }
            }
        }
        __syncthreads();

        // ---- prefetch K(kt+1) (overlaps GEMM2) ----
        if (kt + 1 < NKT) {
            const int c0n = c0t + NT;
            #pragma unroll
            for (int w = 0; w < 2; w++) {
                int c = tid + 256 * w;
                int r = c >> 3, ch = c & 7;
                int rg = c0n + r;
                int rc = rg < LL ? rg : LL - 1;
                cpa16(sb + SK + r * STRB + ch * 16,
                      g_kh + bi + (size_t)rc * DD + ch * 8, rg < LL ? 16 : 0);
            }
        }

        // ---- GEMM2: out += P V (P fp16 single, V fp16 hi+lo: 2-term) ----
        #pragma unroll
        for (int ks = 0; ks < 4; ks++) {
            const uint32_t kb = ks * 32;
            uint32_t pa[2][4], bhi[2][4], blo[2][4];
            #pragma unroll
            for (int a = 0; a < 2; a++) {
                uint32_t ro = (mi * 32 + a * 16 + aRow) * STRB + kb + aSel;
                LDM4(pa[a], sb + SP + ro);
            }
            #pragma unroll
            for (int np = 0; np < 2; np++) {
                uint32_t ro = (ks * 16 + aRow) * STRB + (ni * 32 + np * 16) * 2 + aSel;
                LDM4T(bhi[np], sb + SVHI + ro);
                LDM4T(blo[np], sb + SVLO + ro);
            }
            #pragma unroll
            for (int a = 0; a < 2; a++)
                #pragma unroll
                for (int np = 0; np < 2; np++) {
                    MMAH(oacc[a][2*np],   pa[a], bhi[np][0], bhi[np][1]);
                    MMAH(oacc[a][2*np],   pa[a], blo[np][0], blo[np][1]);
                    MMAH(oacc[a][2*np+1], pa[a], bhi[np][2], bhi[np][3]);
                    MMAH(oacc[a][2*np+1], pa[a], blo[np][2], blo[np][3]);
                }
        }
        __syncthreads();

        // ---- prefetch V(kt+1), commit the K+V group ----
        if (kt + 1 < NKT) {
            const int c0n = c0t + NT;
            #pragma unroll
            for (int w = 0; w < 4; w++) {
                int c = tid + 256 * w;
                int buf = c >> 9;
                int r = (c >> 3) & 63, ch = c & 7;
                int rg = c0n + r;
                int rc = rg < LL ? rg : LL - 1;
                const __half* src = (buf ? g_vlo : g_vhi) + bi + (size_t)rc * DD + ch * 8;
                cpa16(sb + (buf ? SVLO : SVHI) + r * STRB + ch * 16, src, rg < LL ? 16 : 0);
            }
            CP_COMMIT();
        }
    }

    // ---- rowsum reduce -> invl ----
    #pragma unroll
    for (int a = 0; a < 2; a++)
        #pragma unroll
        for (int h = 0; h < 2; h++) {
            float vsum = rs[a][h];
            vsum += __shfl_xor_sync(0xffffffffu, vsum, 1);
            vsum += __shfl_xor_sync(0xffffffffu, vsum, 2);
            if ((l & 3) == 0)
                atomicAdd((float*)(s + SSL) + (mi * 32 + a * 16 + (l >> 2) + 8 * h), vsum);
        }
    __syncthreads();
    if (tid < 128)
        ((float*)(s + SSINV))[tid] = 1.f / ((float*)(s + SSL))[tid];
    __syncthreads();

    const float* sinv = (const float*)(s + SSINV);

    // ---- out = (P V) * invl ----
    #pragma unroll
    for (int a = 0; a < 2; a++) {
        const int R0 = mi * 32 + a * 16 + (l >> 2);
        const float inv0 = sinv[R0], inv1 = sinv[R0 + 8];
        const int r0g = q0 + R0, r1g = r0g + 8;
        #pragma unroll
        for (int nb = 0; nb < 4; nb++) {
            const int d0 = ni * 32 + nb * 8 + 2 * (l & 3);
            if (r0g < LL)
                *(float2*)(out + ((size_t)b * LL + r0g) * DD + d0) =
                    make_float2(oacc[a][nb][0] * inv0, oacc[a][nb][1] * inv0);
            if (r1g < LL)
                *(float2*)(out + ((size_t)b * LL + r1g) * DD + d0) =
                    make_float2(oacc[a][nb][2] * inv1, oacc[a][nb][3] * inv1);
        }
    }

    // ---- fused coalesced score rescale, warp-banded: warp w owns rows
    // [w*16, w*16+16); each warp sweeps its rows' 225 float4s in 512B chunks.
    // Rows were just written by this block -> expected L2-hot.
    {
        const int NC4 = LL / 4;                  // 225 float4s per row
        for (int rr = 0; rr < 16; rr++) {
            const int r  = wid * 16 + rr;
            const int rg = q0 + r;
            if (rg >= LL) break;                 // uniform per warp-band
            const float inv = sinv[r];
            float4* prow = (float4*)(Sb + (size_t)rg * LL);
            #pragma unroll 1
            for (int c4 = l; c4 < NC4; c4 += 32) {
                float4 sv = prow[c4];
                sv.x *= inv; sv.y *= inv; sv.z *= inv; sv.w *= inv;
                prow[c4] = sv;
            }
        }
    }
}

extern "C" void kernel_launch(void* const* d_in, const int* in_sizes, int n_in,
                              void* d_out, int out_size)
{
    const float* q   = (const float*)d_in[0];
    const float* k   = (const float*)d_in[1];
    const float* v   = (const float*)d_in[2];
    const int*   dur = (const int*)d_in[3];

    float* out   = (float*)d_out;
    float* score = out + (size_t)BB * LL * DD;

    const int N4 = NELEM / 4;
    precvt<<<(3 * N4 + 255) / 256, 256>>>(q, k, v);

    cudaFuncSetAttribute(attn_mma, cudaFuncAttributeMaxDynamicSharedMemorySize, SMEM_BYTES);
    dim3 grd(8, BB);
    attn_mma<<<grd, 256, SMEM_BYTES>>>(dur, out, score);
}

// round 14
// speedup vs baseline: 1.3299x; 1.3299x over previous
#include <cuda_runtime.h>
#include <cuda_bf16.h>
#include <cuda_fp16.h>
#include <math.h>
#include <stdint.h>

#define BB 64
#define LL 900
#define DD 64
#define MT 128
#define NT 64
#define NKT 15
#define SC 0.180336893f   // 0.125 * log2(e)

#define STR  72           // 16-bit elems per smem row (144B)
#define STRB 144

// smem byte offsets
#define SQ    0           // Q fp16 single: 128 x 144B
#define SK    18432       // K fp16 single: 64 x 144B
#define SVHI  27648
#define SVLO  36864
#define SP    46080       // P fp16 single: 128 x 144B
#define SSL   64512
#define SSINV 65024
#define SMEM_BYTES 65536

#define NELEM (BB * LL * DD)

__device__ __half g_qh[NELEM];                    // fp16 single
__device__ __half g_kh[NELEM];                    // fp16 single
__device__ __half g_vhi[NELEM], g_vlo[NELEM];     // fp16 split for GEMM2
__device__ __half g_ps[(size_t)BB * LL * LL];     // unnormalized p, fp16 (104 MB scratch)
__device__ float g_invl[BB * LL];

static __device__ __forceinline__ uint32_t smem_u32(const void* p) {
    uint32_t a;
    asm("{ .reg .u64 t; cvta.to.shared.u64 t, %1; cvt.u32.u64 %0, t; }" : "=r"(a) : "l"(p));
    return a;
}
static __device__ __forceinline__ float ex2f(float x) {
    float r; asm("ex2.approx.ftz.f32 %0, %1;" : "=f"(r) : "f"(x)); return r;
}
// pack two f32 -> f16x2
static __device__ __forceinline__ uint32_t cvt2h(float hi, float lo) {
    uint32_t r; asm("cvt.rn.f16x2.f32 %0, %1, %2;" : "=r"(r) : "f"(hi), "f"(lo)); return r;
}
static __device__ __forceinline__ void cpa16(uint32_t dst, const void* src, int sz) {
    asm volatile("cp.async.cg.shared.global [%0], [%1], 16, %2;"
                 :: "r"(dst), "l"(src), "r"(sz) : "memory");
}
#define CP_COMMIT() asm volatile("cp.async.commit_group;" ::: "memory")
#define CP_WAIT0()  asm volatile("cp.async.wait_group 0;" ::: "memory")

#define LDM4(r, a) \
    asm volatile("ldmatrix.sync.aligned.m8n8.x4.shared.b16 {%0,%1,%2,%3}, [%4];" \
        : "=r"((r)[0]), "=r"((r)[1]), "=r"((r)[2]), "=r"((r)[3]) : "r"(a))
#define LDM4T(r, a) \
    asm volatile("ldmatrix.sync.aligned.m8n8.x4.trans.shared.b16 {%0,%1,%2,%3}, [%4];" \
        : "=r"((r)[0]), "=r"((r)[1]), "=r"((r)[2]), "=r"((r)[3]) : "r"(a))
#define MMAH(d, a, b0, b1) \
    asm volatile("mma.sync.aligned.m16n8k16.row.col.f32.f16.f16.f32 " \
        "{%0,%1,%2,%3}, {%4,%5,%6,%7}, {%8,%9}, {%0,%1,%2,%3};" \
        : "+f"((d)[0]), "+f"((d)[1]), "+f"((d)[2]), "+f"((d)[3]) \
        : "r"((a)[0]), "r"((a)[1]), "r"((a)[2]), "r"((a)[3]), "r"(b0), "r"(b1))

// ---------- precvt: q,k -> fp16 single;  v -> fp16 hi/lo ----------
__global__ __launch_bounds__(256)
void precvt(const float* __restrict__ q, const float* __restrict__ k,
            const float* __restrict__ v)
{
    const int N4 = NELEM / 4;
    int i = blockIdx.x * blockDim.x + threadIdx.x;
    if (i >= 3 * N4) return;
    int t  = i / N4;
    int i4 = i - t * N4;
    if (t < 2) {
        float4 val = ((const float4*)(t == 0 ? q : k))[i4];
        uint32_t a01 = cvt2h(val.y, val.x);
        uint32_t a23 = cvt2h(val.w, val.z);
        ((uint2*)(t == 0 ? g_qh : g_kh))[i4] = make_uint2(a01, a23);
    } else {
        float4 val = ((const float4*)v)[i4];
        __half h0 = __float2half(val.x), h1 = __float2half(val.y);
        __half h2 = __float2half(val.z), h3 = __float2half(val.w);
        __half l0 = __float2half(val.x - __half2float(h0));
        __half l1 = __float2half(val.y - __half2float(h1));
        __half l2 = __float2half(val.z - __half2float(h2));
        __half l3 = __float2half(val.w - __half2float(h3));
        __half2 hv0 = __halves2half2(h0, h1), hv1 = __halves2half2(h2, h3);
        __half2 lv0 = __halves2half2(l0, l1), lv1 = __halves2half2(l2, l3);
        ((uint2*)g_vhi)[i4] = make_uint2(*(uint32_t*)&hv0, *(uint32_t*)&hv1);
        ((uint2*)g_vlo)[i4] = make_uint2(*(uint32_t*)&lv0, *(uint32_t*)&lv1);
    }
}

// ---------- fused attention ----------
__global__ void __launch_bounds__(256, 2)
attn_mma(const int* __restrict__ dur, float* __restrict__ out)
{
    extern __shared__ char s[];
    const uint32_t sb = smem_u32(s);

    const int tid = threadIdx.x;
    const int l   = tid & 31;
    const int wid = tid >> 5;
    const int mi  = wid >> 1;
    const int ni  = wid & 1;
    const int b   = blockIdx.y;
    const int q0  = blockIdx.x * MT;
    const int durb = dur[b];
    const size_t bi = (size_t)b * LL * DD;

    __half* Ph = g_ps + (size_t)b * LL * LL;

    if (tid < 128) *(float*)(s + SSL + tid * 4) = 0.f;

    // ---- prologue: cp.async Q + K0 + V0(hi/lo) ----
    #pragma unroll
    for (int w = 0; w < 4; w++) {      // Q: 1024 16B-chunks
        int c = tid + 256 * w;
        int r = c >> 3, ch = c & 7;
        int rg = q0 + r;
        int rc = rg < LL ? rg : LL - 1;
        cpa16(sb + SQ + r * STRB + ch * 16,
              g_qh + bi + (size_t)rc * DD + ch * 8, rg < LL ? 16 : 0);
    }
    #pragma unroll
    for (int w = 0; w < 2; w++) {      // K0: 512 chunks
        int c = tid + 256 * w;
        int r = c >> 3, ch = c & 7;
        cpa16(sb + SK + r * STRB + ch * 16, g_kh + bi + (size_t)r * DD + ch * 8, 16);
    }
    #pragma unroll
    for (int w = 0; w < 4; w++) {      // V0 hi/lo: 1024 chunks
        int c = tid + 256 * w;
        int buf = c >> 9;
        int r = (c >> 3) & 63, ch = c & 7;
        const __half* base = buf ? g_vlo : g_vhi;
        cpa16(sb + (buf ? SVLO : SVHI) + r * STRB + ch * 16,
              base + bi + (size_t)r * DD + ch * 8, 16);
    }
    CP_COMMIT();

    float oacc[2][4][4];
    #pragma unroll
    for (int a = 0; a < 2; a++)
        #pragma unroll
        for (int nb = 0; nb < 4; nb++)
            #pragma unroll
            for (int j = 0; j < 4; j++) oacc[a][nb][j] = 0.f;
    float rs[2][2] = {{0.f, 0.f}, {0.f, 0.f}};

    const uint32_t aSel = (l & 16) ? 16u : 0u;
    const uint32_t bRow = (l & 7) + ((l & 16) ? 8 : 0);
    const uint32_t bSel = (l & 8) ? 16u : 0u;
    const uint32_t aRow = (l & 15);

    for (int kt = 0; kt < NKT; kt++) {
        const int c0t = kt * NT;
        CP_WAIT0();
        __syncthreads();        // tiles ready; prev GEMM2 done

        // ---- GEMM1: S = Q K^T (single fp16) ----
        float sacc[2][4][4];
        #pragma unroll
        for (int a = 0; a < 2; a++)
            #pragma unroll
            for (int nb = 0; nb < 4; nb++)
                #pragma unroll
                for (int j = 0; j < 4; j++) sacc[a][nb][j] = 0.f;

        #pragma unroll
        for (int ks = 0; ks < 4; ks++) {
            const uint32_t kb = ks * 32;
            uint32_t qa[2][4], kf[2][4];
            #pragma unroll
            for (int a = 0; a < 2; a++) {
                uint32_t ro = (mi * 32 + a * 16 + aRow) * STRB + kb + aSel;
                LDM4(qa[a], sb + SQ + ro);
            }
            #pragma unroll
            for (int np = 0; np < 2; np++) {
                uint32_t ro = (ni * 32 + np * 16 + bRow) * STRB + kb + bSel;
                LDM4(kf[np], sb + SK + ro);
            }
            #pragma unroll
            for (int a = 0; a < 2; a++)
                #pragma unroll
                for (int np = 0; np < 2; np++) {
                    MMAH(sacc[a][2*np],   qa[a], kf[np][0], kf[np][1]);
                    MMAH(sacc[a][2*np+1], qa[a], kf[np][2], kf[np][3]);
                }
        }

        // ---- epilogue: p = exp(mask(S*scale)); P(fp16)->smem + fp16 scratch ----
        #pragma unroll
        for (int a = 0; a < 2; a++) {
            const int R0  = mi * 32 + a * 16 + (l >> 2);
            const int r0g = q0 + R0, r1g = r0g + 8;
            #pragma unroll
            for (int nb = 0; nb < 4; nb++) {
                const int col = ni * 32 + nb * 8 + 2 * (l & 3);
                const int cg  = c0t + col;
                float t0 = sacc[a][nb][0] * SC, t1 = sacc[a][nb][1] * SC;
                float t2 = sacc[a][nb][2] * SC, t3 = sacc[a][nb][3] * SC;
                if (r0g >= durb || cg     >= durb) t0 = 0.f;
                if (r0g >= durb || cg + 1 >= durb) t1 = 0.f;
                if (r1g >= durb || cg     >= durb) t2 = 0.f;
                if (r1g >= durb || cg + 1 >= durb) t3 = 0.f;
                float p0 = ex2f(t0), p1 = ex2f(t1), p2 = ex2f(t2), p3 = ex2f(t3);
                if (cg >= LL) { p0 = 0.f; p1 = 0.f; p2 = 0.f; p3 = 0.f; }
                rs[a][0] += p0 + p1;
                rs[a][1] += p2 + p3;
                uint32_t h01 = cvt2h(p1, p0);
                uint32_t h23 = cvt2h(p3, p2);
                uint32_t o0 = (R0 * STR + col) * 2;
                uint32_t o1 = ((R0 + 8) * STR + col) * 2;
                *(uint32_t*)(s + SP + o0) = h01;
                *(uint32_t*)(s + SP + o1) = h23;
                if (cg < LL) {
                    if (r0g < LL) *(uint32_t*)(Ph + (size_t)r0g * LL + cg) = h01;
                    if (r1g < LL) *(uint32_t*)(Ph + (size_t)r1g * LL + cg) = h23;
                }
            }
        }
        __syncthreads();        // P ready; K buffer free

        // ---- prefetch K(kt+1) (overlaps GEMM2) ----
        if (kt + 1 < NKT) {
            const int c0n = c0t + NT;
            #pragma unroll
            for (int w = 0; w < 2; w++) {
                int c = tid + 256 * w;
                int r = c >> 3, ch = c & 7;
                int rg = c0n + r;
                int rc = rg < LL ? rg : LL - 1;
                cpa16(sb + SK + r * STRB + ch * 16,
                      g_kh + bi + (size_t)rc * DD + ch * 8, rg < LL ? 16 : 0);
            }
        }

        // ---- GEMM2: out += P V (P fp16 single, V fp16 hi+lo: 2-term) ----
        #pragma unroll
        for (int ks = 0; ks < 4; ks++) {
            const uint32_t kb = ks * 32;
            uint32_t pa[2][4], bhi[2][4], blo[2][4];
            #pragma unroll
            for (int a = 0; a < 2; a++) {
                uint32_t ro = (mi * 32 + a * 16 + aRow) * STRB + kb + aSel;
                LDM4(pa[a], sb + SP + ro);
            }
            #pragma unroll
            for (int np = 0; np < 2; np++) {
                uint32_t ro = (ks * 16 + aRow) * STRB + (ni * 32 + np * 16) * 2 + aSel;
                LDM4T(bhi[np], sb + SVHI + ro);
                LDM4T(blo[np], sb + SVLO + ro);
            }
            #pragma unroll
            for (int a = 0; a < 2; a++)
                #pragma unroll
                for (int np = 0; np < 2; np++) {
                    MMAH(oacc[a][2*np],   pa[a], bhi[np][0], bhi[np][1]);
                    MMAH(oacc[a][2*np],   pa[a], blo[np][0], blo[np][1]);
                    MMAH(oacc[a][2*np+1], pa[a], bhi[np][2], bhi[np][3]);
                    MMAH(oacc[a][2*np+1], pa[a], blo[np][2], blo[np][3]);
                }
        }
        __syncthreads();        // V/P free

        // ---- prefetch V(kt+1), commit the K+V group ----
        if (kt + 1 < NKT) {
            const int c0n = c0t + NT;
            #pragma unroll
            for (int w = 0; w < 4; w++) {
                int c = tid + 256 * w;
                int buf = c >> 9;
                int r = (c >> 3) & 63, ch = c & 7;
                int rg = c0n + r;
                int rc = rg < LL ? rg : LL - 1;
                const __half* src = (buf ? g_vlo : g_vhi) + bi + (size_t)rc * DD + ch * 8;
                cpa16(sb + (buf ? SVLO : SVHI) + r * STRB + ch * 16, src, rg < LL ? 16 : 0);
            }
            CP_COMMIT();
        }
    }

    // ---- rowsum reduce -> invl ----
    #pragma unroll
    for (int a = 0; a < 2; a++)
        #pragma unroll
        for (int h = 0; h < 2; h++) {
            float vsum = rs[a][h];
            vsum += __shfl_xor_sync(0xffffffffu, vsum, 1);
            vsum += __shfl_xor_sync(0xffffffffu, vsum, 2);
            if ((l & 3) == 0)
                atomicAdd((float*)(s + SSL) + (mi * 32 + a * 16 + (l >> 2) + 8 * h), vsum);
        }
    __syncthreads();
    if (tid < 128) {
        float inv = 1.f / ((float*)(s + SSL))[tid];
        ((float*)(s + SSINV))[tid] = inv;
        int rg = q0 + tid;
        if (rg < LL) g_invl[b * LL + rg] = inv;
    }
    __syncthreads();

    const float* sinv = (const float*)(s + SSINV);

    // ---- out = (P V) * invl ----
    #pragma unroll
    for (int a = 0; a < 2; a++) {
        const int R0 = mi * 32 + a * 16 + (l >> 2);
        const float inv0 = sinv[R0], inv1 = sinv[R0 + 8];
        const int r0g = q0 + R0, r1g = r0g + 8;
        #pragma unroll
        for (int nb = 0; nb < 4; nb++) {
            const int d0 = ni * 32 + nb * 8 + 2 * (l & 3);
            if (r0g < LL)
                *(float2*)(out + ((size_t)b * LL + r0g) * DD + d0) =
                    make_float2(oacc[a][nb][0] * inv0, oacc[a][nb][1] * inv0);
            if (r1g < LL)
                *(float2*)(out + ((size_t)b * LL + r1g) * DD + d0) =
                    make_float2(oacc[a][nb][2] * inv1, oacc[a][nb][3] * inv1);
        }
    }
}

// score = float(g_ps) * invl[row]; thread = 4 halves in, 1 float4 out (900 % 4 == 0)
__global__ __launch_bounds__(256)
void norm_score(float* __restrict__ score)
{
    const int T4 = BB * LL * LL / 4;           // 12,960,000
    int idx = blockIdx.x * blockDim.x + threadIdx.x;
    if (idx >= T4) return;
    int row = idx / (LL / 4);
    const float inv = g_invl[row];
    uint2 hp = ((const uint2*)g_ps)[idx];
    __half2 ha = *(__half2*)&hp.x;
    __half2 hb = *(__half2*)&hp.y;
    float2 fa = __half22float2(ha);
    float2 fb = __half22float2(hb);
    ((float4*)score)[idx] = make_float4(fa.x * inv, fa.y * inv, fb.x * inv, fb.y * inv);
}

extern "C" void kernel_launch(void* const* d_in, const int* in_sizes, int n_in,
                              void* d_out, int out_size)
{
    const float* q   = (const float*)d_in[0];
    const float* k   = (const float*)d_in[1];
    const float* v   = (const float*)d_in[2];
    const int*   dur = (const int*)d_in[3];

    float* out   = (float*)d_out;
    float* score = out + (size_t)BB * LL * DD;

    const int N4 = NELEM / 4;
    precvt<<<(3 * N4 + 255) / 256, 256>>>(q, k, v);

    cudaFuncSetAttribute(attn_mma, cudaFuncAttributeMaxDynamicSharedMemorySize, SMEM_BYTES);
    dim3 grd(8, BB);
    attn_mma<<<grd, 256, SMEM_BYTES>>>(dur, out);

    const int T4 = BB * LL * LL / 4;
    norm_score<<<(T4 + 255) / 256, 256>>>(score);
}

// round 16
// speedup vs baseline: 1.4195x; 1.0674x over previous
#include <cuda_runtime.h>
#include <cuda_bf16.h>
#include <cuda_fp16.h>
#include <math.h>
#include <stdint.h>

#define BB 64
#define LL 900
#define DD 64
#define MT 128
#define NT 64
#define NKT 15
#define SC 0.180336893f   // 0.125 * log2(e)

#define STR  72           // 16-bit elems per smem row (144B)
#define STRB 144

// smem byte offsets
#define SQ    0           // Q fp16 single: 128 x 144B
#define SK    18432       // K fp16 single: 64 x 144B
#define SVHI  27648
#define SVLO  36864
#define SP    46080       // P fp16 single: 128 x 144B
#define SSL   64512
#define SSINV 65024
#define SMEM_BYTES 65536

#define NELEM (BB * LL * DD)

__device__ __half g_qh[NELEM];                    // fp16 single
__device__ __half g_kh[NELEM];                    // fp16 single
__device__ __half g_vhi[NELEM], g_vlo[NELEM];     // fp16 split for GEMM2
__device__ __half g_ps[(size_t)BB * LL * LL];     // unnormalized p, fp16 scratch
__device__ float g_invl[BB * LL];

static __device__ __forceinline__ uint32_t smem_u32(const void* p) {
    uint32_t a;
    asm("{ .reg .u64 t; cvta.to.shared.u64 t, %1; cvt.u32.u64 %0, t; }" : "=r"(a) : "l"(p));
    return a;
}
static __device__ __forceinline__ float ex2f(float x) {
    float r; asm("ex2.approx.ftz.f32 %0, %1;" : "=f"(r) : "f"(x)); return r;
}
static __device__ __forceinline__ uint32_t cvt2h(float hi, float lo) {
    uint32_t r; asm("cvt.rn.f16x2.f32 %0, %1, %2;" : "=r"(r) : "f"(hi), "f"(lo)); return r;
}
static __device__ __forceinline__ void cpa16(uint32_t dst, const void* src, int sz) {
    asm volatile("cp.async.cg.shared.global [%0], [%1], 16, %2;"
                 :: "r"(dst), "l"(src), "r"(sz) : "memory");
}
#define CP_COMMIT() asm volatile("cp.async.commit_group;" ::: "memory")
#define CP_WAIT0()  asm volatile("cp.async.wait_group 0;" ::: "memory")

#define LDM4(r, a) \
    asm volatile("ldmatrix.sync.aligned.m8n8.x4.shared.b16 {%0,%1,%2,%3}, [%4];" \
        : "=r"((r)[0]), "=r"((r)[1]), "=r"((r)[2]), "=r"((r)[3]) : "r"(a))
#define LDM4T(r, a) \
    asm volatile("ldmatrix.sync.aligned.m8n8.x4.trans.shared.b16 {%0,%1,%2,%3}, [%4];" \
        : "=r"((r)[0]), "=r"((r)[1]), "=r"((r)[2]), "=r"((r)[3]) : "r"(a))
#define MMAH(d, a, b0, b1) \
    asm volatile("mma.sync.aligned.m16n8k16.row.col.f32.f16.f16.f32 " \
        "{%0,%1,%2,%3}, {%4,%5,%6,%7}, {%8,%9}, {%0,%1,%2,%3};" \
        : "+f"((d)[0]), "+f"((d)[1]), "+f"((d)[2]), "+f"((d)[3]) \
        : "r"((a)[0]), "r"((a)[1]), "r"((a)[2]), "r"((a)[3]), "r"(b0), "r"(b1))

// ---------- precvt: q,k -> fp16 single;  v -> fp16 hi/lo ----------
__global__ __launch_bounds__(256)
void precvt(const float* __restrict__ q, const float* __restrict__ k,
            const float* __restrict__ v)
{
    const int N4 = NELEM / 4;
    int i = blockIdx.x * blockDim.x + threadIdx.x;
    if (i >= 3 * N4) return;
    int t  = i / N4;
    int i4 = i - t * N4;
    if (t < 2) {
        float4 val = ((const float4*)(t == 0 ? q : k))[i4];
        uint32_t a01 = cvt2h(val.y, val.x);
        uint32_t a23 = cvt2h(val.w, val.z);
        ((uint2*)(t == 0 ? g_qh : g_kh))[i4] = make_uint2(a01, a23);
    } else {
        float4 val = ((const float4*)v)[i4];
        __half h0 = __float2half(val.x), h1 = __float2half(val.y);
        __half h2 = __float2half(val.z), h3 = __float2half(val.w);
        __half l0 = __float2half(val.x - __half2float(h0));
        __half l1 = __float2half(val.y - __half2float(h1));
        __half l2 = __float2half(val.z - __half2float(h2));
        __half l3 = __float2half(val.w - __half2float(h3));
        __half2 hv0 = __halves2half2(h0, h1), hv1 = __halves2half2(h2, h3);
        __half2 lv0 = __halves2half2(l0, l1), lv1 = __halves2half2(l2, l3);
        ((uint2*)g_vhi)[i4] = make_uint2(*(uint32_t*)&hv0, *(uint32_t*)&hv1);
        ((uint2*)g_vlo)[i4] = make_uint2(*(uint32_t*)&lv0, *(uint32_t*)&lv1);
    }
}

// ---------- fused attention ----------
__global__ void __launch_bounds__(256, 2)
attn_mma(const int* __restrict__ dur, float* __restrict__ out)
{
    extern __shared__ char s[];
    const uint32_t sb = smem_u32(s);

    const int tid = threadIdx.x;
    const int l   = tid & 31;
    const int wid = tid >> 5;
    const int mi  = wid >> 1;
    const int ni  = wid & 1;
    const int b   = blockIdx.y;
    const int q0  = blockIdx.x * MT;
    const int durb = dur[b];
    const size_t bi = (size_t)b * LL * DD;
    const bool qmasked = (q0 >= durb);     // whole q-block row-masked

    __half* Ph = g_ps + (size_t)b * LL * LL;

    if (tid < 128) *(float*)(s + SSL + tid * 4) = 0.f;

    // ---- prologue: cp.async Q + K0 + V0(hi/lo) ----
    #pragma unroll
    for (int w = 0; w < 4; w++) {
        int c = tid + 256 * w;
        int r = c >> 3, ch = c & 7;
        int rg = q0 + r;
        int rc = rg < LL ? rg : LL - 1;
        cpa16(sb + SQ + r * STRB + ch * 16,
              g_qh + bi + (size_t)rc * DD + ch * 8, rg < LL ? 16 : 0);
    }
    #pragma unroll
    for (int w = 0; w < 2; w++) {
        int c = tid + 256 * w;
        int r = c >> 3, ch = c & 7;
        cpa16(sb + SK + r * STRB + ch * 16, g_kh + bi + (size_t)r * DD + ch * 8, 16);
    }
    #pragma unroll
    for (int w = 0; w < 4; w++) {
        int c = tid + 256 * w;
        int buf = c >> 9;
        int r = (c >> 3) & 63, ch = c & 7;
        const __half* base = buf ? g_vlo : g_vhi;
        cpa16(sb + (buf ? SVLO : SVHI) + r * STRB + ch * 16,
              base + bi + (size_t)r * DD + ch * 8, 16);
    }
    CP_COMMIT();

    float oacc[2][4][4];
    #pragma unroll
    for (int a = 0; a < 2; a++)
        #pragma unroll
        for (int nb = 0; nb < 4; nb++)
            #pragma unroll
            for (int j = 0; j < 4; j++) oacc[a][nb][j] = 0.f;
    float rs[2][2] = {{0.f, 0.f}, {0.f, 0.f}};

    const uint32_t aSel = (l & 16) ? 16u : 0u;
    const uint32_t bRow = (l & 7) + ((l & 16) ? 8 : 0);
    const uint32_t bSel = (l & 8) ? 16u : 0u;
    const uint32_t aRow = (l & 15);

    for (int kt = 0; kt < NKT; kt++) {
        const int c0t = kt * NT;
        // tile is all-ones (p==1 wherever c<L) iff all rows masked OR all cols masked
        const bool ones = qmasked || (c0t >= durb);
        CP_WAIT0();
        __syncthreads();        // tiles ready; prev GEMM2 done

        if (!ones) {
            // ---- GEMM1: S = Q K^T (single fp16) ----
            float sacc[2][4][4];
            #pragma unroll
            for (int a = 0; a < 2; a++)
                #pragma unroll
                for (int nb = 0; nb < 4; nb++)
                    #pragma unroll
                    for (int j = 0; j < 4; j++) sacc[a][nb][j] = 0.f;

            #pragma unroll
            for (int ks = 0; ks < 4; ks++) {
                const uint32_t kb = ks * 32;
                uint32_t qa[2][4], kf[2][4];
                #pragma unroll
                for (int a = 0; a < 2; a++) {
                    uint32_t ro = (mi * 32 + a * 16 + aRow) * STRB + kb + aSel;
                    LDM4(qa[a], sb + SQ + ro);
                }
                #pragma unroll
                for (int np = 0; np < 2; np++) {
                    uint32_t ro = (ni * 32 + np * 16 + bRow) * STRB + kb + bSel;
                    LDM4(kf[np], sb + SK + ro);
                }
                #pragma unroll
                for (int a = 0; a < 2; a++)
                    #pragma unroll
                    for (int np = 0; np < 2; np++) {
                        MMAH(sacc[a][2*np],   qa[a], kf[np][0], kf[np][1]);
                        MMAH(sacc[a][2*np+1], qa[a], kf[np][2], kf[np][3]);
                    }
            }

            // ---- epilogue: p = exp(mask(S*scale)); P(fp16)->smem + fp16 scratch ----
            #pragma unroll
            for (int a = 0; a < 2; a++) {
                const int R0  = mi * 32 + a * 16 + (l >> 2);
                const int r0g = q0 + R0, r1g = r0g + 8;
                #pragma unroll
                for (int nb = 0; nb < 4; nb++) {
                    const int col = ni * 32 + nb * 8 + 2 * (l & 3);
                    const int cg  = c0t + col;
                    float t0 = sacc[a][nb][0] * SC, t1 = sacc[a][nb][1] * SC;
                    float t2 = sacc[a][nb][2] * SC, t3 = sacc[a][nb][3] * SC;
                    if (r0g >= durb || cg     >= durb) t0 = 0.f;
                    if (r0g >= durb || cg + 1 >= durb) t1 = 0.f;
                    if (r1g >= durb || cg     >= durb) t2 = 0.f;
                    if (r1g >= durb || cg + 1 >= durb) t3 = 0.f;
                    float p0 = ex2f(t0), p1 = ex2f(t1), p2 = ex2f(t2), p3 = ex2f(t3);
                    if (cg >= LL) { p0 = 0.f; p1 = 0.f; p2 = 0.f; p3 = 0.f; }
                    rs[a][0] += p0 + p1;
                    rs[a][1] += p2 + p3;
                    uint32_t h01 = cvt2h(p1, p0);
                    uint32_t h23 = cvt2h(p3, p2);
                    uint32_t o0 = (R0 * STR + col) * 2;
                    uint32_t o1 = ((R0 + 8) * STR + col) * 2;
                    *(uint32_t*)(s + SP + o0) = h01;
                    *(uint32_t*)(s + SP + o1) = h23;
                    if (cg < LL) {
                        if (r0g < LL) *(uint32_t*)(Ph + (size_t)r0g * LL + cg) = h01;
                        if (r1g < LL) *(uint32_t*)(Ph + (size_t)r1g * LL + cg) = h23;
                    }
                }
            }
        } else {
            // ---- all-ones tile: p = 1 (c < L) / 0 (c >= L); no GEMM1, no ex2 ----
            #pragma unroll
            for (int a = 0; a < 2; a++) {
                const int R0  = mi * 32 + a * 16 + (l >> 2);
                const int r0g = q0 + R0, r1g = r0g + 8;
                #pragma unroll
                for (int nb = 0; nb < 4; nb++) {
                    const int col = ni * 32 + nb * 8 + 2 * (l & 3);
                    const int cg  = c0t + col;
                    float p0 = (cg < LL) ? 1.f : 0.f;   // cg, cg+1 same side (LL even, cg even)
                    rs[a][0] += p0 + p0;
                    rs[a][1] += p0 + p0;
                    uint32_t h = p0 != 0.f ? 0x3C003C00u : 0u;   // (1.0h, 1.0h) or zeros
                    uint32_t o0 = (R0 * STR + col) * 2;
                    uint32_t o1 = ((R0 + 8) * STR + col) * 2;
                    *(uint32_t*)(s + SP + o0) = h;
                    *(uint32_t*)(s + SP + o1) = h;
                    if (cg < LL) {
                        if (r0g < LL) *(uint32_t*)(Ph + (size_t)r0g * LL + cg) = h;
                        if (r1g < LL) *(uint32_t*)(Ph + (size_t)r1g * LL + cg) = h;
                    }
                }
            }
        }
        __syncthreads();        // P ready; K buffer free

        // ---- prefetch K(kt+1) (overlaps GEMM2) ----
        if (kt + 1 < NKT) {
            const int c0n = c0t + NT;
            #pragma unroll
            for (int w = 0; w < 2; w++) {
                int c = tid + 256 * w;
                int r = c >> 3, ch = c & 7;
                int rg = c0n + r;
                int rc = rg < LL ? rg : LL - 1;
                cpa16(sb + SK + r * STRB + ch * 16,
                      g_kh + bi + (size_t)rc * DD + ch * 8, rg < LL ? 16 : 0);
            }
        }

        // ---- GEMM2: out += P V (P fp16 single, V fp16 hi+lo: 2-term) ----
        #pragma unroll
        for (int ks = 0; ks < 4; ks++) {
            const uint32_t kb = ks * 32;
            uint32_t pa[2][4], bhi[2][4], blo[2][4];
            #pragma unroll
            for (int a = 0; a < 2; a++) {
                uint32_t ro = (mi * 32 + a * 16 + aRow) * STRB + kb + aSel;
                LDM4(pa[a], sb + SP + ro);
            }
            #pragma unroll
            for (int np = 0; np < 2; np++) {
                uint32_t ro = (ks * 16 + aRow) * STRB + (ni * 32 + np * 16) * 2 + aSel;
                LDM4T(bhi[np], sb + SVHI + ro);
                LDM4T(blo[np], sb + SVLO + ro);
            }
            #pragma unroll
            for (int a = 0; a < 2; a++)
                #pragma unroll
                for (int np = 0; np < 2; np++) {
                    MMAH(oacc[a][2*np],   pa[a], bhi[np][0], bhi[np][1]);
                    MMAH(oacc[a][2*np],   pa[a], blo[np][0], blo[np][1]);
                    MMAH(oacc[a][2*np+1], pa[a], bhi[np][2], bhi[np][3]);
                    MMAH(oacc[a][2*np+1], pa[a], blo[np][2], blo[np][3]);
                }
        }
        __syncthreads();        // V/P free

        // ---- prefetch V(kt+1), commit the K+V group ----
        if (kt + 1 < NKT) {
            const int c0n = c0t + NT;
            #pragma unroll
            for (int w = 0; w < 4; w++) {
                int c = tid + 256 * w;
                int buf = c >> 9;
                int r = (c >> 3) & 63, ch = c & 7;
                int rg = c0n + r;
                int rc = rg < LL ? rg : LL - 1;
                const __half* src = (buf ? g_vlo : g_vhi) + bi + (size_t)rc * DD + ch * 8;
                cpa16(sb + (buf ? SVLO : SVHI) + r * STRB + ch * 16, src, rg < LL ? 16 : 0);
            }
            CP_COMMIT();
        }
    }

    // ---- rowsum reduce -> invl ----
    #pragma unroll
    for (int a = 0; a < 2; a++)
        #pragma unroll
        for (int h = 0; h < 2; h++) {
            float vsum = rs[a][h];
            vsum += __shfl_xor_sync(0xffffffffu, vsum, 1);
            vsum += __shfl_xor_sync(0xffffffffu, vsum, 2);
            if ((l & 3) == 0)
                atomicAdd((float*)(s + SSL) + (mi * 32 + a * 16 + (l >> 2) + 8 * h), vsum);
        }
    __syncthreads();
    if (tid < 128) {
        float inv = 1.f / ((float*)(s + SSL))[tid];
        ((float*)(s + SSINV))[tid] = inv;
        int rg = q0 + tid;
        if (rg < LL) g_invl[b * LL + rg] = inv;
    }
    __syncthreads();

    const float* sinv = (const float*)(s + SSINV);

    // ---- out = (P V) * invl ----
    #pragma unroll
    for (int a = 0; a < 2; a++) {
        const int R0 = mi * 32 + a * 16 + (l >> 2);
        const float inv0 = sinv[R0], inv1 = sinv[R0 + 8];
        const int r0g = q0 + R0, r1g = r0g + 8;
        #pragma unroll
        for (int nb = 0; nb < 4; nb++) {
            const int d0 = ni * 32 + nb * 8 + 2 * (l & 3);
            if (r0g < LL)
                *(float2*)(out + ((size_t)b * LL + r0g) * DD + d0) =
                    make_float2(oacc[a][nb][0] * inv0, oacc[a][nb][1] * inv0);
            if (r1g < LL)
                *(float2*)(out + ((size_t)b * LL + r1g) * DD + d0) =
                    make_float2(oacc[a][nb][2] * inv1, oacc[a][nb][3] * inv1);
        }
    }
}

// score = float(g_ps) * invl[row]; thread = 4 halves in, 1 float4 out
__global__ __launch_bounds__(256)
void norm_score(float* __restrict__ score)
{
    const int T4 = BB * LL * LL / 4;
    int idx = blockIdx.x * blockDim.x + threadIdx.x;
    if (idx >= T4) return;
    int row = idx / (LL / 4);
    const float inv = g_invl[row];
    uint2 hp = ((const uint2*)g_ps)[idx];
    __half2 ha = *(__half2*)&hp.x;
    __half2 hb = *(__half2*)&hp.y;
    float2 fa = __half22float2(ha);
    float2 fb = __half22float2(hb);
    ((float4*)score)[idx] = make_float4(fa.x * inv, fa.y * inv, fb.x * inv, fb.y * inv);
}

extern "C" void kernel_launch(void* const* d_in, const int* in_sizes, int n_in,
                              void* d_out, int out_size)
{
    const float* q   = (const float*)d_in[0];
    const float* k   = (const float*)d_in[1];
    const float* v   = (const float*)d_in[2];
    const int*   dur = (const int*)d_in[3];

    float* out   = (float*)d_out;
    float* score = out + (size_t)BB * LL * DD;

    const int N4 = NELEM / 4;
    precvt<<<(3 * N4 + 255) / 256, 256>>>(q, k, v);

    cudaFuncSetAttribute(attn_mma, cudaFuncAttributeMaxDynamicSharedMemorySize, SMEM_BYTES);
    dim3 grd(8, BB);
    attn_mma<<<grd, 256, SMEM_BYTES>>>(dur, out);

    const int T4 = BB * LL * LL / 4;
    norm_score<<<(T4 + 255) / 256, 256>>>(score);
}

// round 17
// speedup vs baseline: 1.6214x; 1.1423x over previous
#include <cuda_runtime.h>
#include <cuda_bf16.h>
#include <cuda_fp16.h>
#include <math.h>
#include <stdint.h>

#define BB 64
#define LL 900
#define DD 64
#define MT 128
#define NT 64
#define NKT 15
#define SC 0.180336893f   // 0.125 * log2(e)

#define STR  72
#define STRB 144

// smem byte offsets
#define SQ    0
#define SK    18432
#define SVHI  27648
#define SVLO  36864
#define SP    46080
#define SSL   64512
#define SSINV 65024
#define SMEM_BYTES 65536

#define NELEM (BB * LL * DD)

__device__ __half g_qh[NELEM];
__device__ __half g_kh[NELEM];
__device__ __half g_vhi[NELEM], g_vlo[NELEM];
__device__ __half g_ps[(size_t)BB * LL * LL];
__device__ float g_invl[BB * LL];
__device__ float g_sfx[BB * 16 * DD];     // suffix col-sums of V: [b][kt][d], [15]=0

static __device__ __forceinline__ uint32_t smem_u32(const void* p) {
    uint32_t a;
    asm("{ .reg .u64 t; cvta.to.shared.u64 t, %1; cvt.u32.u64 %0, t; }" : "=r"(a) : "l"(p));
    return a;
}
static __device__ __forceinline__ float ex2f(float x) {
    float r; asm("ex2.approx.ftz.f32 %0, %1;" : "=f"(r) : "f"(x)); return r;
}
static __device__ __forceinline__ uint32_t cvt2h(float hi, float lo) {
    uint32_t r; asm("cvt.rn.f16x2.f32 %0, %1, %2;" : "=r"(r) : "f"(hi), "f"(lo)); return r;
}
static __device__ __forceinline__ void cpa16(uint32_t dst, const void* src, int sz) {
    asm volatile("cp.async.cg.shared.global [%0], [%1], 16, %2;"
                 :: "r"(dst), "l"(src), "r"(sz) : "memory");
}
#define CP_COMMIT() asm volatile("cp.async.commit_group;" ::: "memory")
#define CP_WAIT0()  asm volatile("cp.async.wait_group 0;" ::: "memory")

#define LDM4(r, a) \
    asm volatile("ldmatrix.sync.aligned.m8n8.x4.shared.b16 {%0,%1,%2,%3}, [%4];" \
        : "=r"((r)[0]), "=r"((r)[1]), "=r"((r)[2]), "=r"((r)[3]) : "r"(a))
#define LDM4T(r, a) \
    asm volatile("ldmatrix.sync.aligned.m8n8.x4.trans.shared.b16 {%0,%1,%2,%3}, [%4];" \
        : "=r"((r)[0]), "=r"((r)[1]), "=r"((r)[2]), "=r"((r)[3]) : "r"(a))
#define MMAH(d, a, b0, b1) \
    asm volatile("mma.sync.aligned.m16n8k16.row.col.f32.f16.f16.f32 " \
        "{%0,%1,%2,%3}, {%4,%5,%6,%7}, {%8,%9}, {%0,%1,%2,%3};" \
        : "+f"((d)[0]), "+f"((d)[1]), "+f"((d)[2]), "+f"((d)[3]) \
        : "r"((a)[0]), "r"((a)[1]), "r"((a)[2]), "r"((a)[3]), "r"(b0), "r"(b1))

// ---------- precvt: q,k -> fp16 single;  v -> fp16 hi/lo ----------
__global__ __launch_bounds__(256)
void precvt(const float* __restrict__ q, const float* __restrict__ k,
            const float* __restrict__ v)
{
    const int N4 = NELEM / 4;
    int i = blockIdx.x * blockDim.x + threadIdx.x;
    if (i >= 3 * N4) return;
    int t  = i / N4;
    int i4 = i - t * N4;
    if (t < 2) {
        float4 val = ((const float4*)(t == 0 ? q : k))[i4];
        uint32_t a01 = cvt2h(val.y, val.x);
        uint32_t a23 = cvt2h(val.w, val.z);
        ((uint2*)(t == 0 ? g_qh : g_kh))[i4] = make_uint2(a01, a23);
    } else {
        float4 val = ((const float4*)v)[i4];
        __half h0 = __float2half(val.x), h1 = __float2half(val.y);
        __half h2 = __float2half(val.z), h3 = __float2half(val.w);
        __half l0 = __float2half(val.x - __half2float(h0));
        __half l1 = __float2half(val.y - __half2float(h1));
        __half l2 = __float2half(val.z - __half2float(h2));
        __half l3 = __float2half(val.w - __half2float(h3));
        __half2 hv0 = __halves2half2(h0, h1), hv1 = __halves2half2(h2, h3);
        __half2 lv0 = __halves2half2(l0, l1), lv1 = __halves2half2(l2, l3);
        ((uint2*)g_vhi)[i4] = make_uint2(*(uint32_t*)&hv0, *(uint32_t*)&hv1);
        ((uint2*)g_vlo)[i4] = make_uint2(*(uint32_t*)&lv0, *(uint32_t*)&lv1);
    }
}

// ---------- vsuffix: suffix column sums of V per batch (f32 exact) ----------
__global__ __launch_bounds__(64)
void vsuffix(const float* __restrict__ v)
{
    const int b = blockIdx.x;
    const int d = threadIdx.x;
    const float* Vb = v + (size_t)b * LL * DD + d;
    g_sfx[(b * 16 + 15) * DD + d] = 0.f;
    float acc = 0.f;
    for (int kt = NKT - 1; kt >= 0; kt--) {
        int lo = kt * NT;
        int hi = lo + NT < LL ? lo + NT : LL;
        for (int kk = hi - 1; kk >= lo; kk--)
            acc += Vb[(size_t)kk * DD];
        g_sfx[(b * 16 + kt) * DD + d] = acc;
    }
}

// ---------- fused attention ----------
__global__ void __launch_bounds__(256, 2)
attn_mma(const int* __restrict__ dur, float* __restrict__ out)
{
    extern __shared__ char s[];
    const uint32_t sb = smem_u32(s);

    const int tid = threadIdx.x;
    const int l   = tid & 31;
    const int wid = tid >> 5;
    const int mi  = wid >> 1;
    const int ni  = wid & 1;
    const int b   = blockIdx.y;
    const int q0  = blockIdx.x * MT;
    const int durb = dur[b];
    const size_t bi = (size_t)b * LL * DD;
    // tiles needing compute: kt < kt0  (0 if whole q-block is masked)
    const int kt0 = (q0 >= durb) ? 0 : (durb + NT - 1) / NT;

    __half* Ph = g_ps + (size_t)b * LL * LL;

    if (tid < 128) *(float*)(s + SSL + tid * 4) = 0.f;

    // ---- prologue: cp.async Q + K0 + V0(hi/lo) (only if any compute tiles) ----
    if (kt0 > 0) {
        #pragma unroll
        for (int w = 0; w < 4; w++) {
            int c = tid + 256 * w;
            int r = c >> 3, ch = c & 7;
            int rg = q0 + r;
            int rc = rg < LL ? rg : LL - 1;
            cpa16(sb + SQ + r * STRB + ch * 16,
                  g_qh + bi + (size_t)rc * DD + ch * 8, rg < LL ? 16 : 0);
        }
        #pragma unroll
        for (int w = 0; w < 2; w++) {
            int c = tid + 256 * w;
            int r = c >> 3, ch = c & 7;
            cpa16(sb + SK + r * STRB + ch * 16, g_kh + bi + (size_t)r * DD + ch * 8, 16);
        }
        #pragma unroll
        for (int w = 0; w < 4; w++) {
            int c = tid + 256 * w;
            int buf = c >> 9;
            int r = (c >> 3) & 63, ch = c & 7;
            const __half* base = buf ? g_vlo : g_vhi;
            cpa16(sb + (buf ? SVLO : SVHI) + r * STRB + ch * 16,
                  base + bi + (size_t)r * DD + ch * 8, 16);
        }
        CP_COMMIT();
    }

    float oacc[2][4][4];
    #pragma unroll
    for (int a = 0; a < 2; a++)
        #pragma unroll
        for (int nb = 0; nb < 4; nb++)
            #pragma unroll
            for (int j = 0; j < 4; j++) oacc[a][nb][j] = 0.f;
    float rs[2][2] = {{0.f, 0.f}, {0.f, 0.f}};

    const uint32_t aSel = (l & 16) ? 16u : 0u;
    const uint32_t bRow = (l & 7) + ((l & 16) ? 8 : 0);
    const uint32_t bSel = (l & 8) ? 16u : 0u;
    const uint32_t aRow = (l & 15);

    for (int kt = 0; kt < kt0; kt++) {
        const int c0t = kt * NT;
        CP_WAIT0();
        __syncthreads();        // tiles ready; prev GEMM2 done

        // ---- GEMM1: S = Q K^T (single fp16) ----
        float sacc[2][4][4];
        #pragma unroll
        for (int a = 0; a < 2; a++)
            #pragma unroll
            for (int nb = 0; nb < 4; nb++)
                #pragma unroll
                for (int j = 0; j < 4; j++) sacc[a][nb][j] = 0.f;

        #pragma unroll
        for (int ks = 0; ks < 4; ks++) {
            const uint32_t kb = ks * 32;
            uint32_t qa[2][4], kf[2][4];
            #pragma unroll
            for (int a = 0; a < 2; a++) {
                uint32_t ro = (mi * 32 + a * 16 + aRow) * STRB + kb + aSel;
                LDM4(qa[a], sb + SQ + ro);
            }
            #pragma unroll
            for (int np = 0; np < 2; np++) {
                uint32_t ro = (ni * 32 + np * 16 + bRow) * STRB + kb + bSel;
                LDM4(kf[np], sb + SK + ro);
            }
            #pragma unroll
            for (int a = 0; a < 2; a++)
                #pragma unroll
                for (int np = 0; np < 2; np++) {
                    MMAH(sacc[a][2*np],   qa[a], kf[np][0], kf[np][1]);
                    MMAH(sacc[a][2*np+1], qa[a], kf[np][2], kf[np][3]);
                }
        }

        // ---- epilogue: p = exp(mask(S*scale)); P(fp16)->smem + fp16 scratch ----
        #pragma unroll
        for (int a = 0; a < 2; a++) {
            const int R0  = mi * 32 + a * 16 + (l >> 2);
            const int r0g = q0 + R0, r1g = r0g + 8;
            #pragma unroll
            for (int nb = 0; nb < 4; nb++) {
                const int col = ni * 32 + nb * 8 + 2 * (l & 3);
                const int cg  = c0t + col;
                float t0 = sacc[a][nb][0] * SC, t1 = sacc[a][nb][1] * SC;
                float t2 = sacc[a][nb][2] * SC, t3 = sacc[a][nb][3] * SC;
                if (r0g >= durb || cg     >= durb) t0 = 0.f;
                if (r0g >= durb || cg + 1 >= durb) t1 = 0.f;
                if (r1g >= durb || cg     >= durb) t2 = 0.f;
                if (r1g >= durb || cg + 1 >= durb) t3 = 0.f;
                float p0 = ex2f(t0), p1 = ex2f(t1), p2 = ex2f(t2), p3 = ex2f(t3);
                if (cg >= LL) { p0 = 0.f; p1 = 0.f; p2 = 0.f; p3 = 0.f; }
                rs[a][0] += p0 + p1;
                rs[a][1] += p2 + p3;
                uint32_t h01 = cvt2h(p1, p0);
                uint32_t h23 = cvt2h(p3, p2);
                uint32_t o0 = (R0 * STR + col) * 2;
                uint32_t o1 = ((R0 + 8) * STR + col) * 2;
                *(uint32_t*)(s + SP + o0) = h01;
                *(uint32_t*)(s + SP + o1) = h23;
                if (cg < LL) {
                    if (r0g < LL) *(uint32_t*)(Ph + (size_t)r0g * LL + cg) = h01;
                    if (r1g < LL) *(uint32_t*)(Ph + (size_t)r1g * LL + cg) = h23;
                }
            }
        }
        __syncthreads();        // P ready; K buffer free

        // ---- prefetch K(kt+1) (overlaps GEMM2) ----
        if (kt + 1 < kt0) {
            const int c0n = c0t + NT;
            #pragma unroll
            for (int w = 0; w < 2; w++) {
                int c = tid + 256 * w;
                int r = c >> 3, ch = c & 7;
                int rg = c0n + r;
                int rc = rg < LL ? rg : LL - 1;
                cpa16(sb + SK + r * STRB + ch * 16,
                      g_kh + bi + (size_t)rc * DD + ch * 8, rg < LL ? 16 : 0);
            }
        }

        // ---- GEMM2: out += P V (P fp16 single, V fp16 hi+lo: 2-term) ----
        #pragma unroll
        for (int ks = 0; ks < 4; ks++) {
            const uint32_t kb = ks * 32;
            uint32_t pa[2][4], bhi[2][4], blo[2][4];
            #pragma unroll
            for (int a = 0; a < 2; a++) {
                uint32_t ro = (mi * 32 + a * 16 + aRow) * STRB + kb + aSel;
                LDM4(pa[a], sb + SP + ro);
            }
            #pragma unroll
            for (int np = 0; np < 2; np++) {
                uint32_t ro = (ks * 16 + aRow) * STRB + (ni * 32 + np * 16) * 2 + aSel;
                LDM4T(bhi[np], sb + SVHI + ro);
                LDM4T(blo[np], sb + SVLO + ro);
            }
            #pragma unroll
            for (int a = 0; a < 2; a++)
                #pragma unroll
                for (int np = 0; np < 2; np++) {
                    MMAH(oacc[a][2*np],   pa[a], bhi[np][0], bhi[np][1]);
                    MMAH(oacc[a][2*np],   pa[a], blo[np][0], blo[np][1]);
                    MMAH(oacc[a][2*np+1], pa[a], bhi[np][2], bhi[np][3]);
                    MMAH(oacc[a][2*np+1], pa[a], blo[np][2], blo[np][3]);
                }
        }
        __syncthreads();        // V/P free

        // ---- prefetch V(kt+1), commit the K+V group ----
        if (kt + 1 < kt0) {
            const int c0n = c0t + NT;
            #pragma unroll
            for (int w = 0; w < 4; w++) {
                int c = tid + 256 * w;
                int buf = c >> 9;
                int r = (c >> 3) & 63, ch = c & 7;
                int rg = c0n + r;
                int rc = rg < LL ? rg : LL - 1;
                const __half* src = (buf ? g_vlo : g_vhi) + bi + (size_t)rc * DD + ch * 8;
                cpa16(sb + (buf ? SVLO : SVHI) + r * STRB + ch * 16, src, rg < LL ? 16 : 0);
            }
            CP_COMMIT();
        }
    }

    // ---- suffix contribution: all tiles kt >= kt0 are all-ones ----
    const int scnt = (kt0 * NT < LL) ? (LL - kt0 * NT) : 0;   // #ones columns per row
    const float* Sfx = g_sfx + (b * 16 + kt0) * DD;
    float sfx2[4][2];
    #pragma unroll
    for (int nb = 0; nb < 4; nb++) {
        const int d0 = ni * 32 + nb * 8 + 2 * (l & 3);
        sfx2[nb][0] = Sfx[d0];
        sfx2[nb][1] = Sfx[d0 + 1];
    }

    // ---- rowsum reduce -> invl (suffix count added once per row) ----
    #pragma unroll
    for (int a = 0; a < 2; a++)
        #pragma unroll
        for (int h = 0; h < 2; h++) {
            float vsum = rs[a][h];
            vsum += __shfl_xor_sync(0xffffffffu, vsum, 1);
            vsum += __shfl_xor_sync(0xffffffffu, vsum, 2);
            if ((l & 3) == 0)
                atomicAdd((float*)(s + SSL) + (mi * 32 + a * 16 + (l >> 2) + 8 * h), vsum);
        }
    __syncthreads();
    if (tid < 128) {
        float inv = 1.f / (((float*)(s + SSL))[tid] + (float)scnt);
        ((float*)(s + SSINV))[tid] = inv;
        int rg = q0 + tid;
        if (rg < LL) g_invl[b * LL + rg] = inv;
    }
    __syncthreads();

    const float* sinv = (const float*)(s + SSINV);

    // ---- out = (P V + Sfx) * invl ----
    #pragma unroll
    for (int a = 0; a < 2; a++) {
        const int R0 = mi * 32 + a * 16 + (l >> 2);
        const float inv0 = sinv[R0], inv1 = sinv[R0 + 8];
        const int r0g = q0 + R0, r1g = r0g + 8;
        #pragma unroll
        for (int nb = 0; nb < 4; nb++) {
            const int d0 = ni * 32 + nb * 8 + 2 * (l & 3);
            if (r0g < LL)
                *(float2*)(out + ((size_t)b * LL + r0g) * DD + d0) =
                    make_float2((oacc[a][nb][0] + sfx2[nb][0]) * inv0,
                                (oacc[a][nb][1] + sfx2[nb][1]) * inv0);
            if (r1g < LL)
                *(float2*)(out + ((size_t)b * LL + r1g) * DD + d0) =
                    make_float2((oacc[a][nb][2] + sfx2[nb][0]) * inv1,
                                (oacc[a][nb][3] + sfx2[nb][1]) * inv1);
        }
    }
}

// score: ones region synthesized from invl; compute region from fp16 scratch
__global__ __launch_bounds__(256)
void norm_score(float* __restrict__ score, const int* __restrict__ dur)
{
    const int T4 = BB * LL * LL / 4;
    int idx = blockIdx.x * blockDim.x + threadIdx.x;
    if (idx >= T4) return;
    const int row = idx / (LL / 4);
    const int b   = row / LL;
    const int r   = row - b * LL;
    const int c0  = (idx - row * (LL / 4)) * 4;
    const int durb = dur[b];
    const float inv = g_invl[row];
    float4 o;
    if (r >= durb || c0 >= durb) {
        o = make_float4(inv, inv, inv, inv);           // all-ones region: p == 1
    } else {
        uint2 hp = ((const uint2*)g_ps)[idx];
        __half2 ha = *(__half2*)&hp.x;
        __half2 hb = *(__half2*)&hp.y;
        float2 fa = __half22float2(ha);
        float2 fb = __half22float2(hb);
        o = make_float4(fa.x * inv, fa.y * inv, fb.x * inv, fb.y * inv);
        if (c0 + 1 >= durb) o.y = inv;                 // boundary: unwritten -> p == 1
        if (c0 + 2 >= durb) o.z = inv;
        if (c0 + 3 >= durb) o.w = inv;
    }
    ((float4*)score)[idx] = o;
}

extern "C" void kernel_launch(void* const* d_in, const int* in_sizes, int n_in,
                              void* d_out, int out_size)
{
    const float* q   = (const float*)d_in[0];
    const float* k   = (const float*)d_in[1];
    const float* v   = (const float*)d_in[2];
    const int*   dur = (const int*)d_in[3];

    float* out   = (float*)d_out;
    float* score = out + (size_t)BB * LL * DD;

    const int N4 = NELEM / 4;
    precvt<<<(3 * N4 + 255) / 256, 256>>>(q, k, v);
    vsuffix<<<BB, 64>>>(v);

    cudaFuncSetAttribute(attn_mma, cudaFuncAttributeMaxDynamicSharedMemorySize, SMEM_BYTES);
    dim3 grd(8, BB);
    attn_mma<<<grd, 256, SMEM_BYTES>>>(dur, out);

    const int T4 = BB * LL * LL / 4;
    norm_score<<<(T4 + 255) / 256, 256>>>(score, dur);
}